// round 3
// baseline (speedup 1.0000x reference)
#include <cuda_runtime.h>

#define NMAX 16384
#define KNN  16
#define CDIM 64
#define QPB  32     // queries per KNN block
#define GSPL 8      // threads (slices) per query
#define TILE 512    // candidates per smem tile
#define NODES_PER_BLOCK 16

// ---- scratch (no allocation allowed) ----
__device__ float4 g_pos4[NMAX];
__device__ int    g_knn[NMAX * KNN];
__device__ float  g_B[NMAX * CDIM];   // x @ W1b
__device__ float  g_C[NMAX * CDIM];   // x @ (W1a - W1b) + b1

// ============================================================
// Kernel 0: pack pos -> (x,y,z, |p|^2)
// ============================================================
__global__ void pack_pos_kernel(const float* __restrict__ pos, int n) {
    int i = blockIdx.x * blockDim.x + threadIdx.x;
    if (i < n) {
        float x = pos[i * 3 + 0];
        float y = pos[i * 3 + 1];
        float z = pos[i * 3 + 2];
        g_pos4[i] = make_float4(x, y, z, fmaf(x, x, fmaf(y, y, z * z)));
    }
}

// ============================================================
// Kernel 1: brute-force KNN (top-16 smallest squared distances)
// lane = query (32/block), warp = candidate slice (8).
// Register-resident sorted top-16: ONLY static indexing (no local mem).
// ============================================================
__global__ __launch_bounds__(QPB * GSPL, 4)
void knn_kernel(int n) {
    __shared__ float4 tile[TILE];
    // transposed: lists[entry(0..127)][query(0..31)] -> conflict-free merge
    __shared__ unsigned long long lists[GSPL * KNN * QPB];

    const int tid  = threadIdx.x;
    const int w    = tid >> 5;   // slice index 0..7
    const int lane = tid & 31;   // query index within block
    const int q    = blockIdx.x * QPB + lane;

    const float4 qp = g_pos4[q];

    // ascending sorted: best[0] smallest ... best[KNN-1] = current worst
    float best[KNN];
    int   bi[KNN];
#pragma unroll
    for (int r = 0; r < KNN; r++) { best[r] = 3.4e38f; bi[r] = 0; }

    const int cbase = w * (TILE / GSPL);   // 64 candidates per slice per tile

    for (int t0 = 0; t0 < n; t0 += TILE) {
        for (int c = tid; c < TILE; c += QPB * GSPL)
            tile[c] = g_pos4[t0 + c];
        __syncthreads();

#pragma unroll 4
        for (int c = 0; c < TILE / GSPL; c++) {
            float4 p = tile[cbase + c];           // warp broadcast LDS.128
            int   cj = t0 + cbase + c;
            float dot = fmaf(qp.x, p.x, fmaf(qp.y, p.y, qp.z * p.z));
            float dsq = qp.w + p.w - 2.0f * dot;  // same formula as reference
            if (dsq < best[KNN - 1] && cj != q) {
                float dd = fmaxf(dsq, 0.0f);      // keep u64 key ordering valid
                int   ii = cj;
#pragma unroll
                for (int r = 0; r < KNN; r++) {   // static-index bubble insert
                    bool  sw = dd < best[r];
                    float tb = best[r];
                    int   ti = bi[r];
                    best[r] = sw ? dd : tb;
                    bi[r]   = sw ? ii : ti;
                    dd = sw ? tb : dd;
                    ii = sw ? ti : ii;
                }
            }
        }
        __syncthreads();
    }

    // publish local lists as packed (dist<<32 | idx)
#pragma unroll
    for (int r = 0; r < KNN; r++) {
        unsigned long long key =
            ((unsigned long long)__float_as_uint(best[r]) << 32) |
            (unsigned int)bi[r];
        lists[(w * KNN + r) * QPB + lane] = key;
    }
    __syncthreads();

    // merge: thread tid<32 selects 16 smallest of its query's 128 entries
    if (tid < QPB) {
        const int outbase = (blockIdx.x * QPB + tid) * KNN;
        for (int r = 0; r < KNN; r++) {
            unsigned long long m = ~0ULL;
            int mi = 0;
            for (int jj = 0; jj < GSPL * KNN; jj++) {
                unsigned long long v = lists[jj * QPB + tid];
                if (v < m) { m = v; mi = jj; }
            }
            lists[mi * QPB + tid] = ~0ULL;
            g_knn[outbase + r] = (int)(m & 0xffffffffu);
        }
    }
}

// ============================================================
// Kernel 2: B = x @ W1b ; C = x @ (W1a - W1b) + b1
// ============================================================
__global__ void feat_kernel(const float* __restrict__ x,
                            const float* __restrict__ W1,
                            const float* __restrict__ b1, int n) {
    int t = blockIdx.x * blockDim.x + threadIdx.x;
    int nn = t >> 6;
    int d  = t & 63;
    if (nn >= n) return;
    const float* xr = x + nn * CDIM;
    float a = 0.0f, b = 0.0f;
#pragma unroll 8
    for (int c = 0; c < CDIM; c++) {
        float xv = xr[c];                           // warp broadcast, L1-hot
        a = fmaf(xv, W1[c * CDIM + d], a);          // W1a
        b = fmaf(xv, W1[(CDIM + c) * CDIM + d], b); // W1b
    }
    g_B[t] = b;
    g_C[t] = a - b + b1[d];
}

// ============================================================
// Kernel 3: per-node: g[k] = relu(C_i + B_j) for all 16 k (one sync),
// then 16x64 matvec via packed fma.rn.f32x2 + running max.
// thread = output channel d; W2 column pre-packed as 32 f32x2 regs.
// ============================================================
__global__ __launch_bounds__(64)
void edge_kernel(const float* __restrict__ W2,
                 const float* __restrict__ b2,
                 float* __restrict__ out, int n) {
    __shared__ float gs[KNN][CDIM];
    const int d = threadIdx.x;

    // pack W2 column d as 32 f32x2 pairs (W2[2e][d], W2[2e+1][d])
    unsigned long long w2p[CDIM / 2];
#pragma unroll
    for (int e2 = 0; e2 < CDIM / 2; e2++) {
        float a = W2[(2 * e2) * CDIM + d];          // coalesced across d
        float b = W2[(2 * e2 + 1) * CDIM + d];
        asm("mov.b64 %0, {%1, %2};" : "=l"(w2p[e2]) : "f"(a), "f"(b));
    }
    const float b2d = b2[d];

    const int n0 = blockIdx.x * NODES_PER_BLOCK;
    for (int i = 0; i < NODES_PER_BLOCK; i++) {
        const int nn = n0 + i;
        const float cv = g_C[nn * CDIM + d];

        // phase 1: all 16 neighbor features (indices broadcast via L1)
        int j[KNN];
#pragma unroll
        for (int k = 0; k < KNN; k++)
            j[k] = g_knn[nn * KNN + k];
#pragma unroll
        for (int k = 0; k < KNN; k++)
            gs[k][d] = fmaxf(cv + g_B[j[k] * CDIM + d], 0.0f);
        __syncthreads();

        // phase 2: 16 matvecs + max, packed f32x2 FMA
        float m = -3.4e38f;
#pragma unroll
        for (int k = 0; k < KNN; k++) {
            const unsigned long long* gp =
                (const unsigned long long*)gs[k];
            unsigned long long acc = 0ULL;          // {0.f, 0.f}
#pragma unroll
            for (int e2 = 0; e2 < CDIM / 2; e2++) {
                unsigned long long gv = gp[e2];     // LDS.64 broadcast
                asm("fma.rn.f32x2 %0, %1, %2, %3;"
                    : "=l"(acc) : "l"(gv), "l"(w2p[e2]), "l"(acc));
            }
            float lo, hi;
            asm("mov.b64 {%0, %1}, %2;" : "=f"(lo), "=f"(hi) : "l"(acc));
            m = fmaxf(m, lo + hi);
        }
        out[nn * CDIM + d] = m + b2d;
        __syncthreads();   // gs reused next node
    }
}

// ============================================================
extern "C" void kernel_launch(void* const* d_in, const int* in_sizes, int n_in,
                              void* d_out, int out_size) {
    const float* x   = (const float*)d_in[0];
    const float* pos = (const float*)d_in[1];
    const float* W1  = (const float*)d_in[2];
    const float* b1  = (const float*)d_in[3];
    const float* W2  = (const float*)d_in[4];
    const float* b2  = (const float*)d_in[5];
    float* out = (float*)d_out;

    int n = in_sizes[1] / 3;
    if (n > NMAX) n = NMAX;

    pack_pos_kernel<<<(n + 255) / 256, 256>>>(pos, n);
    knn_kernel<<<n / QPB, QPB * GSPL>>>(n);
    feat_kernel<<<(n * CDIM + 255) / 256, 256>>>(x, W1, b1, n);
    edge_kernel<<<n / NODES_PER_BLOCK, CDIM>>>(W2, b2, out, n);
}

// round 4
// speedup vs baseline: 2.9487x; 2.9487x over previous
#include <cuda_runtime.h>

#define NMAX 16384
#define KNN  16
#define CDIM 64
#define NODES_PER_BLOCK 4

#define KNN_WARPS 16          // queries per block (one warp each)
#define KNN_THREADS (KNN_WARPS * 32)
#define KNN_TILE 2048         // candidates per smem tile (32KB)

#define FULLMASK 0xffffffffu
#define FINF __int_as_float(0x7f800000)

// ---- scratch (no allocation allowed) ----
__device__ float4 g_pos4[NMAX];
__device__ int    g_knn[NMAX * KNN];
__device__ float  g_B[NMAX * CDIM];   // x @ W1b
__device__ float  g_C[NMAX * CDIM];   // x @ (W1a - W1b) + b1

// ============================================================
// Kernel 0: pack pos -> (x,y,z, |p|^2)
// ============================================================
__global__ void pack_pos_kernel(const float* __restrict__ pos, int n) {
    int i = blockIdx.x * blockDim.x + threadIdx.x;
    if (i < n) {
        float x = pos[i * 3 + 0];
        float y = pos[i * 3 + 1];
        float z = pos[i * 3 + 2];
        g_pos4[i] = make_float4(x, y, z, fmaf(x, x, fmaf(y, y, z * z)));
    }
}

// ============================================================
// Kernel 1: brute-force KNN — warp per query.
// Warp-distributed sorted top-16: lane l (<16) holds l-th smallest.
// Inserts are warp-uniform (the divergence killer in R2/R3 is gone):
// per candidate batch of 32 we do one ballot against the EXACT current
// 16th-smallest; each passing candidate is inserted by the whole warp
// via shfl-up shift (~16 instrs, expected ~111 inserts per query).
// ============================================================
__global__ __launch_bounds__(KNN_THREADS, 4)
void knn_kernel(int n) {
    __shared__ float4 tile[KNN_TILE];

    const int tid  = threadIdx.x;
    const int w    = tid >> 5;
    const int lane = tid & 31;
    const int q    = blockIdx.x * KNN_WARPS + w;

    const float4 qp = g_pos4[q];

    float bd = FINF;      // lane<16: l-th smallest distance
    int   bj = 0;
    float worst = FINF;   // current 16th smallest (warp-uniform)

    for (int t0 = 0; t0 < n; t0 += KNN_TILE) {
        for (int c = tid; c < KNN_TILE; c += KNN_THREADS)
            tile[c] = g_pos4[t0 + c];
        __syncthreads();

#pragma unroll 4
        for (int it = 0; it < KNN_TILE; it += 32) {
            float4 p = tile[it + lane];
            int   cj = t0 + it + lane;
            float dot = fmaf(qp.x, p.x, fmaf(qp.y, p.y, qp.z * p.z));
            float dsq = fmaf(-2.0f, dot, qp.w + p.w);  // same formula as ref
            if (cj == q) dsq = FINF;                   // self-exclusion

            unsigned m = __ballot_sync(FULLMASK, dsq < worst);
            while (m) {
                int src = __ffs(m) - 1;
                m &= m - 1;
                float dn = __shfl_sync(FULLMASK, dsq, src);  // warp-uniform
                if (dn < worst) {   // uniform branch (worst tightens in-loop)
                    int jn = t0 + it + src;
                    float bd_prev = __shfl_up_sync(FULLMASK, bd, 1);
                    int   bj_prev = __shfl_up_sync(FULLMASK, bj, 1);
                    unsigned gm = __ballot_sync(FULLMASK,
                                                (lane < KNN) && (bd > dn));
                    int pos = __ffs(gm) - 1;   // gm != 0 since bd[15] > dn
                    if (lane < KNN) {
                        if (lane > pos)       { bd = bd_prev; bj = bj_prev; }
                        else if (lane == pos) { bd = dn;      bj = jn; }
                    }
                    worst = __shfl_sync(FULLMASK, bd, KNN - 1);
                }
            }
        }
        __syncthreads();
    }

    if (lane < KNN)
        g_knn[q * KNN + lane] = bj;
}

// ============================================================
// Kernel 2: B = x @ W1b ; C = x @ (W1a - W1b) + b1
// ============================================================
__global__ void feat_kernel(const float* __restrict__ x,
                            const float* __restrict__ W1,
                            const float* __restrict__ b1, int n) {
    int t = blockIdx.x * blockDim.x + threadIdx.x;
    int nn = t >> 6;
    int d  = t & 63;
    if (nn >= n) return;
    const float* xr = x + nn * CDIM;
    float a = 0.0f, b = 0.0f;
#pragma unroll 8
    for (int c = 0; c < CDIM; c++) {
        float xv = xr[c];                           // warp broadcast, L1-hot
        a = fmaf(xv, W1[c * CDIM + d], a);          // W1a
        b = fmaf(xv, W1[(CDIM + c) * CDIM + d], b); // W1b
    }
    g_B[t] = b;
    g_C[t] = a - b + b1[d];
}

// ============================================================
// Kernel 3: per-node: g[k] = relu(C_i + B_j) for all 16 k (one sync),
// then 16x64 matvec via packed fma.rn.f32x2 + running max.
// thread = output channel d; W2 column pre-packed as 32 f32x2 regs.
// Dual accumulators break the serial FMA chain; grid enlarged 4x for occ.
// ============================================================
__global__ __launch_bounds__(64)
void edge_kernel(const float* __restrict__ W2,
                 const float* __restrict__ b2,
                 float* __restrict__ out, int n) {
    __shared__ float gs[KNN][CDIM];
    const int d = threadIdx.x;

    // pack W2 column d as 32 f32x2 pairs (W2[2e][d], W2[2e+1][d])
    unsigned long long w2p[CDIM / 2];
#pragma unroll
    for (int e2 = 0; e2 < CDIM / 2; e2++) {
        float a = W2[(2 * e2) * CDIM + d];          // coalesced across d
        float b = W2[(2 * e2 + 1) * CDIM + d];
        asm("mov.b64 %0, {%1, %2};" : "=l"(w2p[e2]) : "f"(a), "f"(b));
    }
    const float b2d = b2[d];

    const int n0 = blockIdx.x * NODES_PER_BLOCK;
    for (int i = 0; i < NODES_PER_BLOCK; i++) {
        const int nn = n0 + i;
        const float cv = g_C[nn * CDIM + d];

        int j[KNN];
#pragma unroll
        for (int k = 0; k < KNN; k++)
            j[k] = g_knn[nn * KNN + k];             // uniform, L1 broadcast
#pragma unroll
        for (int k = 0; k < KNN; k++)
            gs[k][d] = fmaxf(cv + g_B[j[k] * CDIM + d], 0.0f);
        __syncthreads();

        float m = -3.4e38f;
#pragma unroll
        for (int k = 0; k < KNN; k++) {
            const unsigned long long* gp = (const unsigned long long*)gs[k];
            unsigned long long acc0 = 0ULL, acc1 = 0ULL;
#pragma unroll
            for (int e2 = 0; e2 < CDIM / 2; e2 += 2) {
                unsigned long long gv0 = gp[e2];       // LDS.64 broadcast
                unsigned long long gv1 = gp[e2 + 1];
                asm("fma.rn.f32x2 %0, %1, %2, %3;"
                    : "=l"(acc0) : "l"(gv0), "l"(w2p[e2]), "l"(acc0));
                asm("fma.rn.f32x2 %0, %1, %2, %3;"
                    : "=l"(acc1) : "l"(gv1), "l"(w2p[e2 + 1]), "l"(acc1));
            }
            float lo0, hi0, lo1, hi1;
            asm("mov.b64 {%0, %1}, %2;" : "=f"(lo0), "=f"(hi0) : "l"(acc0));
            asm("mov.b64 {%0, %1}, %2;" : "=f"(lo1), "=f"(hi1) : "l"(acc1));
            m = fmaxf(m, (lo0 + hi0) + (lo1 + hi1));
        }
        out[nn * CDIM + d] = m + b2d;
        __syncthreads();   // gs reused next node
    }
}

// ============================================================
extern "C" void kernel_launch(void* const* d_in, const int* in_sizes, int n_in,
                              void* d_out, int out_size) {
    const float* x   = (const float*)d_in[0];
    const float* pos = (const float*)d_in[1];
    const float* W1  = (const float*)d_in[2];
    const float* b1  = (const float*)d_in[3];
    const float* W2  = (const float*)d_in[4];
    const float* b2  = (const float*)d_in[5];
    float* out = (float*)d_out;

    int n = in_sizes[1] / 3;
    if (n > NMAX) n = NMAX;

    pack_pos_kernel<<<(n + 255) / 256, 256>>>(pos, n);
    knn_kernel<<<n / KNN_WARPS, KNN_THREADS>>>(n);
    feat_kernel<<<(n * CDIM + 255) / 256, 256>>>(x, W1, b1, n);
    edge_kernel<<<n / NODES_PER_BLOCK, CDIM>>>(W2, b2, out, n);
}